// round 11
// baseline (speedup 1.0000x reference)
#include <cuda_runtime.h>

#define PMAX 32
#define COUT 64
#define GRID 296
#define NTHR 512
#define NWARP 16
#define VPBMAX 160
#define SLABW 192          // floats per voxel in smem slab (16 pairs * 12 words)
#define EPSV 1e-5f

// Scratch (no allocations): per-block partials + barrier state.
__device__ float g_part[GRID * 16];
__device__ unsigned g_count = 0;     // arrive counter (returns to 0 each launch)
__device__ unsigned g_release = 0;   // monotonically increasing generation

typedef unsigned long long u64;

__device__ __forceinline__ u64 pk2(float a, float b) {
    u64 r; asm("mov.b64 %0, {%1,%2};" : "=l"(r) : "f"(a), "f"(b)); return r;
}
__device__ __forceinline__ void upk2(u64 v, float& a, float& b) {
    asm("mov.b64 {%0,%1}, %2;" : "=f"(a), "=f"(b) : "l"(v));
}
__device__ __forceinline__ u64 fma2(u64 a, u64 b, u64 c) {
    u64 d; asm("fma.rn.f32x2 %0, %1, %2, %3;" : "=l"(d) : "l"(a), "l"(b), "l"(c)); return d;
}

extern __shared__ float sm_slab[];   // vpb * SLABW floats (dynamic, ~104 KB)

__global__ void __launch_bounds__(NTHR, 2) fused_kernel(
    const float* __restrict__ feat, const int* __restrict__ npts,
    const float* __restrict__ W, const float* __restrict__ b,
    const float* __restrict__ gamma, const float* __restrict__ beta,
    float* __restrict__ out, int M, int vpb)
{
    __shared__ int sm_n[VPBMAX];
    __shared__ float red[32][16];
    __shared__ float fin[16];

    int tid = threadIdx.x;
    int w = tid >> 5, l = tid & 31;
    int vb = blockIdx.x * vpb;

    for (int i = tid; i < vpb; i += NTHR)
        sm_n[i] = (vb + i < M) ? __ldg(&npts[vb + i]) : 0;
    __syncthreads();

    // ===== Phase A: load feat ONCE -> stats + stage slab (zeros padded) =====
    float cnt = 0.f;
    float s0=0,s1=0,s2=0,s3=0;
    float q00=0,q01=0,q02=0,q03=0,q11=0,q12=0,q13=0,q22=0,q23=0,q33=0;

    const float4* fbase = ((const float4*)feat) + (size_t)vb * PMAX;
    int slots = vpb * PMAX;
    #pragma unroll 4
    for (int i = tid; i < slots; i += NTHR) {
        int m = i >> 5, p = i & 31;
        bool ok = (p < sm_n[m]);
        float4 v = make_float4(0.f, 0.f, 0.f, 0.f);
        if (ok) v = __ldg(&fbase[i]);
        cnt += ok ? 1.f : 0.f;
        float* d = sm_slab + m * SLABW + (p >> 1) * 12 + (p & 1);
        d[0] = v.x; d[2] = v.y; d[4] = v.z; d[6] = v.w;
        s0 += v.x; s1 += v.y; s2 += v.z; s3 += v.w;
        q00 += v.x*v.x; q01 += v.x*v.y; q02 += v.x*v.z; q03 += v.x*v.w;
        q11 += v.y*v.y; q12 += v.y*v.z; q13 += v.y*v.w;
        q22 += v.z*v.z; q23 += v.z*v.w; q33 += v.w*v.w;
    }

    float vals[15] = {cnt, s0,s1,s2,s3, q00,q01,q02,q03,q11,q12,q13,q22,q23,q33};
    #pragma unroll
    for (int k = 0; k < 15; k++) {
        #pragma unroll
        for (int off = 16; off > 0; off >>= 1)
            vals[k] += __shfl_down_sync(0xffffffffu, vals[k], off);
    }
    if (l == 0) {
        #pragma unroll
        for (int k = 0; k < 15; k++) red[w][k] = vals[k];
    }
    __syncthreads();
    if (tid < 15) {
        float t = 0.f;
        #pragma unroll
        for (int ww = 0; ww < NWARP; ww++) t += red[ww][tid];
        g_part[blockIdx.x * 16 + tid] = t;
        __threadfence();
    }
    __syncthreads();

    // ================= Grid barrier (deterministic) =========================
    if (tid == 0) {
        unsigned old = *((volatile unsigned*)&g_release);
        unsigned a = atomicAdd(&g_count, 1);
        if (a == gridDim.x - 1) {
            g_count = 0;
            __threadfence();
            *((volatile unsigned*)&g_release) = old + 1;
        } else {
            while (*((volatile unsigned*)&g_release) == old) { }
            __threadfence();
        }
    }
    __syncthreads();

    // ================= Fold: every block reduces all partials ===============
    {
        int stat = tid & 15, grp = tid >> 4;     // 32 groups of 16 stats
        float s = 0.f;
        for (int k = grp; k < (int)gridDim.x; k += 32)
            s += g_part[k * 16 + stat];
        red[grp][stat] = s;
    }
    __syncthreads();
    if (tid < 16) {
        float tt = 0.f;
        #pragma unroll
        for (int g = 0; g < 32; g++) tt += red[g][tid];
        fin[tid] = tt;
    }
    __syncthreads();

    // Per-thread BN fold for channels o0 = l and o1 = l + 32.
    float N  = fmaxf(fin[0], 1.f);
    float invN = 1.f / N;
    float S0 = fin[1], S1 = fin[2], S2 = fin[3], S3 = fin[4];
    float f00=fin[5], f01=fin[6], f02=fin[7], f03=fin[8];
    float f11=fin[9], f12=fin[10], f13=fin[11];
    float f22=fin[12], f23=fin[13], f33=fin[14];

    u64 WA0, WA1, WA2, WA3, WB0, WB1, WB2, WB3, BA, BB;
    float relu0A, relu0B;
    #pragma unroll
    for (int half = 0; half < 2; half++) {
        int o = l + half * 32;
        float w0 = __ldg(&W[o*4+0]), w1 = __ldg(&W[o*4+1]);
        float w2 = __ldg(&W[o*4+2]), w3 = __ldg(&W[o*4+3]);
        float bo = __ldg(&b[o]);
        float wS = w0*S0 + w1*S1 + w2*S2 + w3*S3;
        float mu = (wS + bo * N) * invN;
        float wQw = w0*(f00*w0 + f01*w1 + f02*w2 + f03*w3)
                  + w1*(f01*w0 + f11*w1 + f12*w2 + f13*w3)
                  + w2*(f02*w0 + f12*w1 + f22*w2 + f23*w3)
                  + w3*(f03*w0 + f13*w1 + f23*w2 + f33*w3);
        float Eh2 = (wQw + 2.f*bo*wS + bo*bo*N) * invN;
        float var = fmaxf(Eh2 - mu*mu, 0.f);
        float sc  = __ldg(&gamma[o]) * rsqrtf(var + EPSV);
        float bf  = sc * (bo - mu) + __ldg(&beta[o]);
        if (half == 0) {
            WA0 = pk2(sc*w0, sc*w0); WA1 = pk2(sc*w1, sc*w1);
            WA2 = pk2(sc*w2, sc*w2); WA3 = pk2(sc*w3, sc*w3);
            BA = pk2(bf, bf); relu0A = fmaxf(bf, 0.f);
        } else {
            WB0 = pk2(sc*w0, sc*w0); WB1 = pk2(sc*w1, sc*w1);
            WB2 = pk2(sc*w2, sc*w2); WB3 = pk2(sc*w3, sc*w3);
            BB = pk2(bf, bf); relu0B = fmaxf(bf, 0.f);
        }
    }
    u64 H2 = pk2(0.5f, 0.5f);
    const u64 ABSM = 0x7FFFFFFF7FFFFFFFULL;

    // ===== Phase B: TWO voxels per warp iteration (4 indep chains) ==========
    for (int mv = w; mv < vpb; mv += 2 * NWARP) {
        int m1 = vb + mv;
        if (m1 >= M) break;                       // warp-uniform
        int mv2 = mv + NWARP;
        bool has2 = (mv2 < vpb) && (vb + mv2 < M);
        int n1 = sm_n[mv];
        int n2 = has2 ? sm_n[mv2] : 0;
        const float* sA = sm_slab + mv * SLABW;
        const float* sB = sm_slab + (has2 ? mv2 : mv) * SLABW;
        int P1 = ((n1 + 7) >> 3) << 2;            // pairs, multiple of 4
        int P2 = ((n2 + 7) >> 3) << 2;
        int P  = P1 > P2 ? P1 : P2;               // shared trip count (exact: pads are zero)

        u64 A1 = 0ULL, B1 = 0ULL, A2 = 0ULL, B2 = 0ULL;
        for (int j = 0; j < P; j += 2) {
            #pragma unroll
            for (int jj = 0; jj < 2; jj++) {
                const ulonglong2* qa = reinterpret_cast<const ulonglong2*>(sA + (j + jj) * 12);
                const ulonglong2* qb = reinterpret_cast<const ulonglong2*>(sB + (j + jj) * 12);
                ulonglong2 qa0 = qa[0], qa1 = qa[1];
                ulonglong2 qb0 = qb[0], qb1 = qb[1];
                // voxel-1 channels A/B
                u64 h1A = fma2(WA0, qa0.x, BA);
                u64 h1B = fma2(WB0, qa0.x, BB);
                u64 h2A = fma2(WA0, qb0.x, BA);
                u64 h2B = fma2(WB0, qb0.x, BB);
                h1A = fma2(WA1, qa0.y, h1A);
                h1B = fma2(WB1, qa0.y, h1B);
                h2A = fma2(WA1, qb0.y, h2A);
                h2B = fma2(WB1, qb0.y, h2B);
                h1A = fma2(WA2, qa1.x, h1A);
                h1B = fma2(WB2, qa1.x, h1B);
                h2A = fma2(WA2, qb1.x, h2A);
                h2B = fma2(WB2, qb1.x, h2B);
                h1A = fma2(WA3, qa1.y, h1A);
                h1B = fma2(WB3, qa1.y, h1B);
                h2A = fma2(WA3, qb1.y, h2A);
                h2B = fma2(WB3, qb1.y, h2B);
                A1 = fma2(H2, h1A, A1); A1 = fma2(H2, h1A & ABSM, A1);
                B1 = fma2(H2, h1B, B1); B1 = fma2(H2, h1B & ABSM, B1);
                A2 = fma2(H2, h2A, A2); A2 = fma2(H2, h2A & ABSM, A2);
                B2 = fma2(H2, h2B, B2); B2 = fma2(H2, h2B & ABSM, B2);
            }
        }

        float r0, r1;
        upk2(A1, r0, r1); float a1 = r0 + r1;
        upk2(B1, r0, r1); float b1 = r0 + r1;
        // Padded slots (zeros) each contribute relu(b'); subtract exactly.
        float e1 = (float)(2 * P - n1);
        a1 = fmaf(-e1, relu0A, a1);
        b1 = fmaf(-e1, relu0B, b1);
        float inv1 = 1.f / fmaxf((float)n1, 1.f);
        out[(size_t)m1 * COUT + l]      = a1 * inv1;
        out[(size_t)m1 * COUT + 32 + l] = b1 * inv1;

        if (has2) {
            int m2 = vb + mv2;
            upk2(A2, r0, r1); float a2 = r0 + r1;
            upk2(B2, r0, r1); float b2 = r0 + r1;
            float e2 = (float)(2 * P - n2);
            a2 = fmaf(-e2, relu0A, a2);
            b2 = fmaf(-e2, relu0B, b2);
            float inv2 = 1.f / fmaxf((float)n2, 1.f);
            out[(size_t)m2 * COUT + l]      = a2 * inv2;
            out[(size_t)m2 * COUT + 32 + l] = b2 * inv2;
        }
    }
}

// ---------------------------------------------------------------------------
extern "C" void kernel_launch(void* const* d_in, const int* in_sizes, int n_in,
                              void* d_out, int out_size)
{
    const float* feat  = (const float*)d_in[0];
    const int*   npts  = (const int*)d_in[1];
    const float* W     = (const float*)d_in[2];
    const float* b     = (const float*)d_in[3];
    const float* gamma = (const float*)d_in[4];
    const float* beta  = (const float*)d_in[5];
    float* out = (float*)d_out;
    int M = in_sizes[1];

    int vpb = (M + GRID - 1) / GRID;        // 136 for M=40000
    if (vpb > VPBMAX) vpb = VPBMAX;          // (problem shape fixed; stays in range)
    size_t dynbytes = (size_t)vpb * SLABW * sizeof(float);   // ~104 KB

    static int attr_done = 0;                // idempotent attribute set (host-side)
    if (!attr_done) {
        cudaFuncSetAttribute(fused_kernel,
                             cudaFuncAttributeMaxDynamicSharedMemorySize,
                             VPBMAX * SLABW * (int)sizeof(float));
        attr_done = 1;
    }

    fused_kernel<<<GRID, NTHR, dynbytes>>>(feat, npts, W, b, gamma, beta, out, M, vpb);
}

// round 12
// speedup vs baseline: 1.1132x; 1.1132x over previous
#include <cuda_runtime.h>

#define PMAX 32
#define COUT 64
#define GRID 296
#define NTHR 512
#define NWARP 16
#define VPBMAX 160
#define SLABW 192          // floats per voxel in smem slab (16 pairs * 12 words)
#define EPSV 1e-5f

// Scratch (no allocations): per-block partials + barrier state.
__device__ float g_part[GRID * 16];
__device__ unsigned g_count = 0;     // arrive counter (returns to 0 each launch)
__device__ unsigned g_release = 0;   // monotonically increasing generation

typedef unsigned long long u64;

__device__ __forceinline__ u64 pk2(float a, float b) {
    u64 r; asm("mov.b64 %0, {%1,%2};" : "=l"(r) : "f"(a), "f"(b)); return r;
}
__device__ __forceinline__ void upk2(u64 v, float& a, float& b) {
    asm("mov.b64 {%0,%1}, %2;" : "=f"(a), "=f"(b) : "l"(v));
}
__device__ __forceinline__ u64 fma2(u64 a, u64 b, u64 c) {
    u64 d; asm("fma.rn.f32x2 %0, %1, %2, %3;" : "=l"(d) : "l"(a), "l"(b), "l"(c)); return d;
}
__device__ __forceinline__ u64 add2(u64 a, u64 b) {
    u64 d; asm("add.rn.f32x2 %0, %1, %2;" : "=l"(d) : "l"(a), "l"(b)); return d;
}

extern __shared__ float sm_slab[];   // vpb * SLABW + pad floats (dynamic, ~104 KB)

__global__ void __launch_bounds__(NTHR, 2) fused_kernel(
    const float* __restrict__ feat, const int* __restrict__ npts,
    const float* __restrict__ W, const float* __restrict__ b,
    const float* __restrict__ gamma, const float* __restrict__ beta,
    float* __restrict__ out, int M, int vpb)
{
    __shared__ int sm_n[VPBMAX];
    __shared__ float red[32][16];
    __shared__ float fin[16];

    int tid = threadIdx.x;
    int w = tid >> 5, l = tid & 31;
    int vb = blockIdx.x * vpb;

    for (int i = tid; i < vpb; i += NTHR)
        sm_n[i] = (vb + i < M) ? __ldg(&npts[vb + i]) : 0;
    __syncthreads();

    // ===== Phase A: load feat ONCE -> stats + stage slab (zeros padded) =====
    float cnt = 0.f;
    float s0=0,s1=0,s2=0,s3=0;
    float q00=0,q01=0,q02=0,q03=0,q11=0,q12=0,q13=0,q22=0,q23=0,q33=0;

    const float4* fbase = ((const float4*)feat) + (size_t)vb * PMAX;
    int slots = vpb * PMAX;
    #pragma unroll 4
    for (int i = tid; i < slots; i += NTHR) {
        int m = i >> 5, p = i & 31;
        bool ok = (p < sm_n[m]);
        float4 v = make_float4(0.f, 0.f, 0.f, 0.f);
        if (ok) v = __ldg(&fbase[i]);
        cnt += ok ? 1.f : 0.f;
        float* d = sm_slab + m * SLABW + (p >> 1) * 12 + (p & 1);
        d[0] = v.x; d[2] = v.y; d[4] = v.z; d[6] = v.w;
        s0 += v.x; s1 += v.y; s2 += v.z; s3 += v.w;
        q00 += v.x*v.x; q01 += v.x*v.y; q02 += v.x*v.z; q03 += v.x*v.w;
        q11 += v.y*v.y; q12 += v.y*v.z; q13 += v.y*v.w;
        q22 += v.z*v.z; q23 += v.z*v.w; q33 += v.w*v.w;
    }

    float vals[15] = {cnt, s0,s1,s2,s3, q00,q01,q02,q03,q11,q12,q13,q22,q23,q33};
    #pragma unroll
    for (int k = 0; k < 15; k++) {
        #pragma unroll
        for (int off = 16; off > 0; off >>= 1)
            vals[k] += __shfl_down_sync(0xffffffffu, vals[k], off);
    }
    if (l == 0) {
        #pragma unroll
        for (int k = 0; k < 15; k++) red[w][k] = vals[k];
    }
    __syncthreads();
    if (tid < 15) {
        float t = 0.f;
        #pragma unroll
        for (int ww = 0; ww < NWARP; ww++) t += red[ww][tid];
        g_part[blockIdx.x * 16 + tid] = t;
        __threadfence();
    }
    __syncthreads();

    // ================= Grid barrier (deterministic) =========================
    if (tid == 0) {
        unsigned old = *((volatile unsigned*)&g_release);
        unsigned a = atomicAdd(&g_count, 1);
        if (a == gridDim.x - 1) {
            g_count = 0;
            __threadfence();
            *((volatile unsigned*)&g_release) = old + 1;
        } else {
            while (*((volatile unsigned*)&g_release) == old) { }
            __threadfence();
        }
    }
    __syncthreads();

    // ================= Fold: every block reduces all partials ===============
    {
        int stat = tid & 15, grp = tid >> 4;     // 32 groups of 16 stats
        float s = 0.f;
        for (int k = grp; k < (int)gridDim.x; k += 32)
            s += g_part[k * 16 + stat];
        red[grp][stat] = s;
    }
    __syncthreads();
    if (tid < 16) {
        float tt = 0.f;
        #pragma unroll
        for (int g = 0; g < 32; g++) tt += red[g][tid];
        fin[tid] = tt;
    }
    __syncthreads();

    // Per-thread BN fold for channels o0 = l and o1 = l + 32.
    float N  = fmaxf(fin[0], 1.f);
    float invN = 1.f / N;
    float S0 = fin[1], S1 = fin[2], S2 = fin[3], S3 = fin[4];
    float f00=fin[5], f01=fin[6], f02=fin[7], f03=fin[8];
    float f11=fin[9], f12=fin[10], f13=fin[11];
    float f22=fin[12], f23=fin[13], f33=fin[14];

    u64 WA0, WA1, WA2, WA3, WB0, WB1, WB2, WB3, BA, BB;
    float relu0A, relu0B;
    #pragma unroll
    for (int half = 0; half < 2; half++) {
        int o = l + half * 32;
        float w0 = __ldg(&W[o*4+0]), w1 = __ldg(&W[o*4+1]);
        float w2 = __ldg(&W[o*4+2]), w3 = __ldg(&W[o*4+3]);
        float bo = __ldg(&b[o]);
        float wS = w0*S0 + w1*S1 + w2*S2 + w3*S3;
        float mu = (wS + bo * N) * invN;
        float wQw = w0*(f00*w0 + f01*w1 + f02*w2 + f03*w3)
                  + w1*(f01*w0 + f11*w1 + f12*w2 + f13*w3)
                  + w2*(f02*w0 + f12*w1 + f22*w2 + f23*w3)
                  + w3*(f03*w0 + f13*w1 + f23*w2 + f33*w3);
        float Eh2 = (wQw + 2.f*bo*wS + bo*bo*N) * invN;
        float var = fmaxf(Eh2 - mu*mu, 0.f);
        float sc  = __ldg(&gamma[o]) * rsqrtf(var + EPSV);
        float bf  = sc * (bo - mu) + __ldg(&beta[o]);
        if (half == 0) {
            WA0 = pk2(sc*w0, sc*w0); WA1 = pk2(sc*w1, sc*w1);
            WA2 = pk2(sc*w2, sc*w2); WA3 = pk2(sc*w3, sc*w3);
            BA = pk2(bf, bf); relu0A = fmaxf(bf, 0.f);
        } else {
            WB0 = pk2(sc*w0, sc*w0); WB1 = pk2(sc*w1, sc*w1);
            WB2 = pk2(sc*w2, sc*w2); WB3 = pk2(sc*w3, sc*w3);
            BB = pk2(bf, bf); relu0B = fmaxf(bf, 0.f);
        }
    }
    const u64 ABSM = 0x7FFFFFFF7FFFFFFFULL;

    // ===== Phase B: warp-per-voxel, software-pipelined, split accumulators ==
    for (int mv = w; mv < vpb; mv += NWARP) {
        int m = vb + mv;
        if (m >= M) break;                       // warp-uniform
        int n = sm_n[mv];
        const float* s = sm_slab + mv * SLABW;
        int P = (n + 1) >> 1;                    // exact pairs (half-pair slot is zero)

        // Prime pair 0.
        const ulonglong2* q = reinterpret_cast<const ulonglong2*>(s);
        ulonglong2 c0 = q[0], c1 = q[1];

        u64 SHA = 0ULL, SABA = 0ULL, SHB = 0ULL, SABB = 0ULL;
        for (int j = 0; j < P; j++) {
            // Prefetch pair j+1 (slab padded: always in-bounds, dead on last iter).
            const ulonglong2* qn = reinterpret_cast<const ulonglong2*>(s + (j + 1) * 12);
            ulonglong2 n0 = qn[0], n1 = qn[1];

            u64 hA = fma2(WA0, c0.x, BA);
            u64 hB = fma2(WB0, c0.x, BB);
            hA = fma2(WA1, c0.y, hA);
            hB = fma2(WB1, c0.y, hB);
            hA = fma2(WA2, c1.x, hA);
            hB = fma2(WB2, c1.x, hB);
            hA = fma2(WA3, c1.y, hA);
            hB = fma2(WB3, c1.y, hB);
            SHA  = add2(SHA, hA);                // independent 4-cyc chain
            SABA = add2(SABA, hA & ABSM);        // independent 4-cyc chain
            SHB  = add2(SHB, hB);
            SABB = add2(SABB, hB & ABSM);

            c0 = n0; c1 = n1;
        }

        // relu-sum = 0.5*(sum h + sum |h|), then fold packed halves.
        float r0, r1, r2, r3;
        upk2(SHA, r0, r1); upk2(SABA, r2, r3);
        float acc0 = 0.5f * ((r0 + r1) + (r2 + r3));
        upk2(SHB, r0, r1); upk2(SABB, r2, r3);
        float acc1 = 0.5f * ((r0 + r1) + (r2 + r3));

        // Padded zero slots each contributed relu(b'); subtract exactly.
        float extra = (float)(2 * P - n);        // 0 or 1
        acc0 = fmaf(-extra, relu0A, acc0);
        acc1 = fmaf(-extra, relu0B, acc1);

        float inv = 1.f / fmaxf((float)n, 1.f);
        out[(size_t)m * COUT + l]      = acc0 * inv;
        out[(size_t)m * COUT + 32 + l] = acc1 * inv;
    }
}

// ---------------------------------------------------------------------------
extern "C" void kernel_launch(void* const* d_in, const int* in_sizes, int n_in,
                              void* d_out, int out_size)
{
    const float* feat  = (const float*)d_in[0];
    const int*   npts  = (const int*)d_in[1];
    const float* W     = (const float*)d_in[2];
    const float* b     = (const float*)d_in[3];
    const float* gamma = (const float*)d_in[4];
    const float* beta  = (const float*)d_in[5];
    float* out = (float*)d_out;
    int M = in_sizes[1];

    int vpb = (M + GRID - 1) / GRID;        // 136 for M=40000
    if (vpb > VPBMAX) vpb = VPBMAX;          // (problem shape fixed; stays in range)
    // +16 floats: prefetch of pair P (dead value) must stay in-bounds.
    size_t dynbytes = ((size_t)vpb * SLABW + 16) * sizeof(float);

    static int attr_done = 0;                // idempotent attribute set (host-side)
    if (!attr_done) {
        cudaFuncSetAttribute(fused_kernel,
                             cudaFuncAttributeMaxDynamicSharedMemorySize,
                             (VPBMAX * SLABW + 16) * (int)sizeof(float));
        attr_done = 1;
    }

    fused_kernel<<<GRID, NTHR, dynbytes>>>(feat, npts, W, b, gamma, beta, out, M, vpb);
}